// round 9
// baseline (speedup 1.0000x reference)
#include <cuda_runtime.h>

#define NMIX 160
// gemm1: 64m x 160n, KC=64, 512 threads = 4m x 4n warps, j=5
#define T1    512
#define BM1   64
#define KC1   64
#define A1PAD 68     // mod 32 = 4  (A-frag conflict-free)
#define B1PAD 168    // mod 32 = 8  (B-frag conflict-free)
#define XK_SZ (BM1 * A1PAD)
#define W1_SZ (KC1 * B1PAD)
#define SM1_FLOATS (2 * XK_SZ + 2 * W1_SZ)       // 30208 -> 120832 B
// gemm2: 64m x 64d, 256 threads = 4m x 2n warps, j=4
#define T2    256
#define BM2   64
#define BN2   64
#define HPAD  164    // mod 32 = 4
#define WPAD  72     // mod 32 = 8
#define YPAD  68     // y restage pad (aliases h buffer)
#define SM2_FLOATS (BM2 * HPAD + NMIX * WPAD)     // 22016 -> 88064 B

// h = tanh(xk @ W1): [M][NMIX], M = 8192
__device__ float g_h[8192 * NMIX];

__device__ __forceinline__ void mma_tf32(float* c, const float4& a, const float2& b) {
    const unsigned* A = reinterpret_cast<const unsigned*>(&a);
    const unsigned* B = reinterpret_cast<const unsigned*>(&b);
    asm volatile(
        "mma.sync.aligned.m16n8k8.row.col.f32.tf32.tf32.f32 "
        "{%0,%1,%2,%3},{%4,%5,%6,%7},{%8,%9},{%0,%1,%2,%3};"
        : "+f"(c[0]), "+f"(c[1]), "+f"(c[2]), "+f"(c[3])
        : "r"(A[0]), "r"(A[1]), "r"(A[2]), "r"(A[3]), "r"(B[0]), "r"(B[1]));
}

// ---------------------------------------------------------------------------
// GEMM1: g_h[m,n] = tanh( sum_k xk[m,k] * W1[k,n] )
// single barrier per chunk; raw f32 operands (HW tf32 truncation)
// ---------------------------------------------------------------------------
__global__ void __launch_bounds__(T1, 1) k_gemm1(
    const float* __restrict__ x, const float* __restrict__ state,
    const float* __restrict__ tmx, const float* __restrict__ W1,
    const int* __restrict__ i_ptr, int S, int D, int rows)
{
    extern __shared__ float sm[];

    const int m0g  = blockIdx.x * BM1;
    const int tid  = threadIdx.x;
    const int w    = tid >> 5;
    const int lane = tid & 31;
    const int wm   = w & 3;
    const int wn   = w >> 2;
    const int gq   = lane >> 2;
    const int tig  = lane & 3;
    const int i1   = rows * i_ptr[0] + 1;

    const int sa_m  = tid >> 4;          // 0..31 (+32 on 2nd iter)
    const int sa_kq = (tid & 15) * 4;

    float acc[5][4];
#pragma unroll
    for (int j = 0; j < 5; j++)
#pragma unroll
        for (int q = 0; q < 4; q++) acc[j][q] = 0.f;

    float4 xv[2], pv[2], tv[2];
    float4 wv[5];
    int    wk[5], wn4[5];

    const int nc = D / KC1;

#define LDG1(KB)                                                              \
    {                                                                         \
        _Pragma("unroll")                                                     \
        for (int it = 0; it < 2; it++) {                                      \
            int m  = sa_m + it * 32;                                          \
            int mg = m0g + m;                                                 \
            int g  = (KB) + sa_kq;                                            \
            xv[it] = *(const float4*)&x[(size_t)mg * D + g];                  \
            if ((mg % S) == 0) {                                              \
                int b = mg / S;                                               \
                pv[it] = *(const float4*)&state[((size_t)b * rows + i1) * D + g]; \
            } else {                                                          \
                pv[it] = *(const float4*)&x[(size_t)(mg - 1) * D + g];        \
            }                                                                 \
            tv[it] = *(const float4*)&tmx[g];                                 \
        }                                                                     \
        _Pragma("unroll")                                                     \
        for (int it = 0; it < 5; it++) {                                      \
            int idx = tid + it * T1;                                          \
            int k   = idx / 40;                                               \
            int n4  = (idx - k * 40) * 4;                                     \
            wk[it] = k; wn4[it] = n4;                                         \
            wv[it] = *(const float4*)&W1[(size_t)((KB) + k) * NMIX + n4];     \
        }                                                                     \
    }

#define STS1(BUF)                                                             \
    {                                                                         \
        float* xb = sm + (BUF) * XK_SZ;                                       \
        float* wb = sm + 2 * XK_SZ + (BUF) * W1_SZ;                           \
        _Pragma("unroll")                                                     \
        for (int it = 0; it < 2; it++) {                                      \
            int m = sa_m + it * 32;                                           \
            float4 v;                                                         \
            v.x = xv[it].x + (pv[it].x - xv[it].x) * tv[it].x;                \
            v.y = xv[it].y + (pv[it].y - xv[it].y) * tv[it].y;                \
            v.z = xv[it].z + (pv[it].z - xv[it].z) * tv[it].z;                \
            v.w = xv[it].w + (pv[it].w - xv[it].w) * tv[it].w;                \
            *(float4*)&xb[m * A1PAD + sa_kq] = v;                             \
        }                                                                     \
        _Pragma("unroll")                                                     \
        for (int it = 0; it < 5; it++)                                        \
            *(float4*)&wb[wk[it] * B1PAD + wn4[it]] = wv[it];                 \
    }

    LDG1(0);

    for (int c = 0; c < nc; c++) {
        STS1(c & 1);
        __syncthreads();
        if (c + 1 < nc) LDG1((c + 1) * KC1);

        const float* xb = sm + (c & 1) * XK_SZ;
        const float* wb = sm + 2 * XK_SZ + (c & 1) * W1_SZ;
        const int r0 = wm * 16 + gq;
#pragma unroll
        for (int ks = 0; ks < 8; ks++) {
            const int k0 = ks * 8;
            float4 af;
            af.x = xb[r0 * A1PAD + k0 + tig];
            af.y = xb[(r0 + 8) * A1PAD + k0 + tig];
            af.z = xb[r0 * A1PAD + k0 + tig + 4];
            af.w = xb[(r0 + 8) * A1PAD + k0 + tig + 4];
#pragma unroll
            for (int j = 0; j < 5; j++) {
                const int n = wn * 40 + j * 8 + gq;
                float2 b;
                b.x = wb[(k0 + tig) * B1PAD + n];
                b.y = wb[(k0 + tig + 4) * B1PAD + n];
                mma_tf32(acc[j], af, b);
            }
        }
    }

    const int r0g = m0g + wm * 16 + gq;
#pragma unroll
    for (int j = 0; j < 5; j++) {
        const int n = wn * 40 + j * 8 + tig * 2;
        *(float2*)&g_h[(size_t)r0g * NMIX + n] =
            make_float2(tanhf(acc[j][0]), tanhf(acc[j][1]));
        *(float2*)&g_h[(size_t)(r0g + 8) * NMIX + n] =
            make_float2(tanhf(acc[j][2]), tanhf(acc[j][3]));
    }
#undef LDG1
#undef STS1
}

// ---------------------------------------------------------------------------
// GEMM2 fused: out[m,f,d] = x + sx*(maa_f + h_f @ W2_f)
// 64m x 64d blocks; per-f y restage through smem -> coalesced float4 I/O.
// ---------------------------------------------------------------------------
__global__ void __launch_bounds__(T2, 2) k_gemm2(
    const float* __restrict__ x, const float* __restrict__ state,
    const float* __restrict__ W2,
    const float* __restrict__ mk, const float* __restrict__ mw,
    const float* __restrict__ mv, const float* __restrict__ mr,
    const float* __restrict__ mg,
    const int* __restrict__ i_ptr, float* __restrict__ out,
    float* __restrict__ out_state,
    int S, int D, int rows, int has_state, int total4)
{
    extern __shared__ float sm[];
    float* h_s = sm;                 // [64][HPAD] ; later aliased as y[64][YPAD]
    float* w2s = sm + BM2 * HPAD;    // [160][WPAD]

    const int m0   = blockIdx.x * BM2;
    const int d0   = blockIdx.y * BN2;
    const int tid  = threadIdx.x;
    const int w    = tid >> 5;
    const int lane = tid & 31;
    const int wm   = w & 3;          // 4 m-groups of 16
    const int wn   = w >> 2;         // 2 n-groups of 32
    const int gq   = lane >> 2;
    const int tig  = lane & 3;
    const int i1   = rows * i_ptr[0] + 1;

    // ---- state copy (distributed over all blocks) ----
    if (has_state) {
        const int nb = gridDim.x * gridDim.y;
        for (int idx = (blockIdx.y * gridDim.x + blockIdx.x) * T2 + tid;
             idx < total4; idx += nb * T2) {
            int e  = idx * 4;
            int dd = e % D;
            int r  = (e / D) % rows;
            int b  = e / (D * rows);
            float4 v;
            if (r == i1)
                v = *(const float4*)&x[((size_t)b * S + (S - 1)) * D + dd];
            else
                v = *(const float4*)&state[e];
            *(float4*)&out_state[e] = v;
        }
    }

    // ---- stage h (64x160) and W2 (160x64) ----
#pragma unroll
    for (int it = 0; it < 10; it++) {
        int idx = tid + it * T2;
        int r   = idx / 40;
        int c4  = (idx - r * 40) * 4;
        *(float4*)&h_s[r * HPAD + c4] = *(const float4*)&g_h[(size_t)(m0 + r) * NMIX + c4];
    }
#pragma unroll
    for (int it = 0; it < 10; it++) {
        int idx = tid + it * T2;
        int k   = idx >> 4;
        int n4  = (idx & 15) * 4;
        *(float4*)&w2s[k * WPAD + n4] = *(const float4*)&W2[(size_t)k * D + d0 + n4];
    }
    __syncthreads();

    // ---- MMA: all 5 modes ----
    float acc[5][4][4];
#pragma unroll
    for (int f = 0; f < 5; f++)
#pragma unroll
        for (int j = 0; j < 4; j++)
#pragma unroll
            for (int q = 0; q < 4; q++) acc[f][j][q] = 0.f;

    {
        const int r0 = wm * 16 + gq;
#pragma unroll
        for (int f = 0; f < 5; f++) {
#pragma unroll
            for (int ks = 0; ks < 4; ks++) {
                const int kc = f * 32 + ks * 8;
                float4 af;
                af.x = h_s[r0 * HPAD + kc + tig];
                af.y = h_s[(r0 + 8) * HPAD + kc + tig];
                af.z = h_s[r0 * HPAD + kc + tig + 4];
                af.w = h_s[(r0 + 8) * HPAD + kc + tig + 4];
#pragma unroll
                for (int j = 0; j < 4; j++) {
                    const int n = wn * 32 + j * 8 + gq;
                    float2 b;
                    b.x = w2s[(kc + tig) * WPAD + n];
                    b.y = w2s[(kc + tig + 4) * WPAD + n];
                    mma_tf32(acc[f][j], af, b);
                }
            }
        }
    }

    // ---- coalesced epilogue: thread -> 4 rows x 4 consecutive d ----
    const int ed4 = (tid & 15) * 4;        // d offset (0..60)
    const int em0 = tid >> 4;              // base row (0..15), rows em0+16*it

    float4 xr[4], sxr[4];
#pragma unroll
    for (int it = 0; it < 4; it++) {
        const int mr_ = m0 + em0 + it * 16;
        xr[it] = *(const float4*)&x[(size_t)mr_ * D + d0 + ed4];
        float4 pvv;
        if ((mr_ % S) == 0) {
            int b = mr_ / S;
            pvv = *(const float4*)&state[((size_t)b * rows + i1) * D + d0 + ed4];
        } else {
            pvv = *(const float4*)&x[(size_t)(mr_ - 1) * D + d0 + ed4];
        }
        sxr[it].x = pvv.x - xr[it].x;
        sxr[it].y = pvv.y - xr[it].y;
        sxr[it].z = pvv.z - xr[it].z;
        sxr[it].w = pvv.w - xr[it].w;
    }

    const float* maa[5] = { mk, mw, mv, mr, mg };
    float* ys = sm;    // y[64][YPAD], aliases h_s (dead after MMA)

#pragma unroll 1
    for (int f = 0; f < 5; f++) {
        __syncthreads();    // h_s/y reads of previous phase complete
        // STS y from fragments
#pragma unroll
        for (int j = 0; j < 4; j++) {
            const int col = wn * 32 + j * 8 + tig * 2;
#pragma unroll
            for (int half = 0; half < 2; half++) {
                const int row = wm * 16 + gq + half * 8;
                *(float2*)&ys[row * YPAD + col] =
                    make_float2(acc[f][j][half * 2], acc[f][j][half * 2 + 1]);
            }
        }
        __syncthreads();

        const float4 mfv = *(const float4*)&maa[f][d0 + ed4];
#pragma unroll
        for (int it = 0; it < 4; it++) {
            const int row = em0 + it * 16;
            const int mr_ = m0 + row;
            const float4 yv = *(const float4*)&ys[row * YPAD + ed4];
            float4 o;
            o.x = xr[it].x + sxr[it].x * (mfv.x + yv.x);
            o.y = xr[it].y + sxr[it].y * (mfv.y + yv.y);
            o.z = xr[it].z + sxr[it].z * (mfv.z + yv.z);
            o.w = xr[it].w + sxr[it].w * (mfv.w + yv.w);
            *(float4*)&out[((size_t)mr_ * 5 + f) * D + d0 + ed4] = o;
        }
    }
}

// ---------------------------------------------------------------------------
extern "C" void kernel_launch(void* const* d_in, const int* in_sizes, int n_in,
                              void* d_out, int out_size)
{
    const float* x     = (const float*)d_in[0];
    const float* state = (const float*)d_in[1];
    const float* tmx   = (const float*)d_in[2];
    const float* W1    = (const float*)d_in[3];
    const float* W2    = (const float*)d_in[4];
    const float* mk    = (const float*)d_in[5];
    const float* mw    = (const float*)d_in[6];
    const float* mv    = (const float*)d_in[7];
    const float* mr    = (const float*)d_in[8];
    const float* mg    = (const float*)d_in[9];
    const int*   ip    = (const int*)d_in[10];

    const int D    = in_sizes[2];          // 2048
    const int M    = in_sizes[0] / D;      // 8192
    const int rows = 2 + D / 32;           // 66
    const int B    = in_sizes[1] / (rows * D);
    const int S    = M / B;

    float* out_x = (float*)d_out;
    const long long xsz = (long long)M * 5 * D;
    const int has_state = ((long long)out_size > xsz) ? 1 : 0;
    float* out_state = out_x + xsz;
    const int total4 = (B * rows * D) / 4;

    const int smem1 = SM1_FLOATS * 4;      // 120832 B
    const int smem2 = SM2_FLOATS * 4;      // 88064 B
    static int inited = 0;
    if (!inited) {
        cudaFuncSetAttribute(k_gemm1, cudaFuncAttributeMaxDynamicSharedMemorySize, smem1);
        cudaFuncSetAttribute(k_gemm2, cudaFuncAttributeMaxDynamicSharedMemorySize, smem2);
        inited = 1;
    }

    k_gemm1<<<M / BM1, T1, smem1>>>(x, state, tmx, W1, ip, S, D, rows);

    dim3 g2(M / BM2, D / BN2);
    k_gemm2<<<g2, T2, smem2>>>(x, state, W2, mk, mw, mv, mr, mg, ip,
                               out_x, out_state, S, D, rows,
                               has_state, total4);
}

// round 10
// speedup vs baseline: 1.3038x; 1.3038x over previous
#include <cuda_runtime.h>

#define NMIX 160
// gemm1: 64m x 160n, KC=64, 512 threads = 4m x 4n warps, j=5
#define T1    512
#define BM1   64
#define KC1   64
#define A1PAD 68     // mod 32 = 4  (A-frag conflict-free)
#define B1PAD 168    // mod 32 = 8  (B-frag conflict-free)
#define XK_SZ (BM1 * A1PAD)
#define W1_SZ (KC1 * B1PAD)
#define SM1_FLOATS (2 * XK_SZ + 2 * W1_SZ)       // 30208 -> 120832 B
// gemm2: 64m x 256d blocks; W2 streamed in 32-wide double-buffered chunks
#define T2    256
#define BM2   64
#define BN2   256
#define CW    32                     // chunk width
#define NCH   (BN2 / CW)             // 8
#define HPAD  164                    // mod 32 = 4
#define WPAD2 40                     // mod 32 = 8
#define HS_SZ (BM2 * HPAD)                       // 10496
#define WB_SZ (NMIX * WPAD2)                     // 6400
#define SM2_FLOATS (HS_SZ + 2 * WB_SZ)           // 23296 -> 93184 B

// h = tanh(xk @ W1): [M][NMIX], M = 8192
__device__ float g_h[8192 * NMIX];

__device__ __forceinline__ void mma_tf32(float* c, const float4& a, const float2& b) {
    const unsigned* A = reinterpret_cast<const unsigned*>(&a);
    const unsigned* B = reinterpret_cast<const unsigned*>(&b);
    asm volatile(
        "mma.sync.aligned.m16n8k8.row.col.f32.tf32.tf32.f32 "
        "{%0,%1,%2,%3},{%4,%5,%6,%7},{%8,%9},{%0,%1,%2,%3};"
        : "+f"(c[0]), "+f"(c[1]), "+f"(c[2]), "+f"(c[3])
        : "r"(A[0]), "r"(A[1]), "r"(A[2]), "r"(A[3]), "r"(B[0]), "r"(B[1]));
}

// ---------------------------------------------------------------------------
// GEMM1: g_h[m,n] = tanh( sum_k xk[m,k] * W1[k,n] )
// ---------------------------------------------------------------------------
__global__ void __launch_bounds__(T1, 1) k_gemm1(
    const float* __restrict__ x, const float* __restrict__ state,
    const float* __restrict__ tmx, const float* __restrict__ W1,
    const int* __restrict__ i_ptr, int S, int D, int rows)
{
    extern __shared__ float sm[];

    const int m0g  = blockIdx.x * BM1;
    const int tid  = threadIdx.x;
    const int w    = tid >> 5;
    const int lane = tid & 31;
    const int wm   = w & 3;
    const int wn   = w >> 2;
    const int gq   = lane >> 2;
    const int tig  = lane & 3;
    const int i1   = rows * i_ptr[0] + 1;

    const int sa_m  = tid >> 4;
    const int sa_kq = (tid & 15) * 4;

    float acc[5][4];
#pragma unroll
    for (int j = 0; j < 5; j++)
#pragma unroll
        for (int q = 0; q < 4; q++) acc[j][q] = 0.f;

    float4 xv[2], pv[2], tv[2];
    float4 wv[5];
    int    wk[5], wn4[5];

    const int nc = D / KC1;

#define LDG1(KB)                                                              \
    {                                                                         \
        _Pragma("unroll")                                                     \
        for (int it = 0; it < 2; it++) {                                      \
            int m  = sa_m + it * 32;                                          \
            int mg = m0g + m;                                                 \
            int g  = (KB) + sa_kq;                                            \
            xv[it] = *(const float4*)&x[(size_t)mg * D + g];                  \
            if ((mg % S) == 0) {                                              \
                int b = mg / S;                                               \
                pv[it] = *(const float4*)&state[((size_t)b * rows + i1) * D + g]; \
            } else {                                                          \
                pv[it] = *(const float4*)&x[(size_t)(mg - 1) * D + g];        \
            }                                                                 \
            tv[it] = *(const float4*)&tmx[g];                                 \
        }                                                                     \
        _Pragma("unroll")                                                     \
        for (int it = 0; it < 5; it++) {                                      \
            int idx = tid + it * T1;                                          \
            int k   = idx / 40;                                               \
            int n4  = (idx - k * 40) * 4;                                     \
            wk[it] = k; wn4[it] = n4;                                         \
            wv[it] = *(const float4*)&W1[(size_t)((KB) + k) * NMIX + n4];     \
        }                                                                     \
    }

#define STS1(BUF)                                                             \
    {                                                                         \
        float* xb = sm + (BUF) * XK_SZ;                                       \
        float* wb = sm + 2 * XK_SZ + (BUF) * W1_SZ;                           \
        _Pragma("unroll")                                                     \
        for (int it = 0; it < 2; it++) {                                      \
            int m = sa_m + it * 32;                                           \
            float4 v;                                                         \
            v.x = xv[it].x + (pv[it].x - xv[it].x) * tv[it].x;                \
            v.y = xv[it].y + (pv[it].y - xv[it].y) * tv[it].y;                \
            v.z = xv[it].z + (pv[it].z - xv[it].z) * tv[it].z;                \
            v.w = xv[it].w + (pv[it].w - xv[it].w) * tv[it].w;                \
            *(float4*)&xb[m * A1PAD + sa_kq] = v;                             \
        }                                                                     \
        _Pragma("unroll")                                                     \
        for (int it = 0; it < 5; it++)                                        \
            *(float4*)&wb[wk[it] * B1PAD + wn4[it]] = wv[it];                 \
    }

    LDG1(0);

    for (int c = 0; c < nc; c++) {
        STS1(c & 1);
        __syncthreads();
        if (c + 1 < nc) LDG1((c + 1) * KC1);

        const float* xb = sm + (c & 1) * XK_SZ;
        const float* wb = sm + 2 * XK_SZ + (c & 1) * W1_SZ;
        const int r0 = wm * 16 + gq;
#pragma unroll
        for (int ks = 0; ks < 8; ks++) {
            const int k0 = ks * 8;
            float4 af;
            af.x = xb[r0 * A1PAD + k0 + tig];
            af.y = xb[(r0 + 8) * A1PAD + k0 + tig];
            af.z = xb[r0 * A1PAD + k0 + tig + 4];
            af.w = xb[(r0 + 8) * A1PAD + k0 + tig + 4];
#pragma unroll
            for (int j = 0; j < 5; j++) {
                const int n = wn * 40 + j * 8 + gq;
                float2 b;
                b.x = wb[(k0 + tig) * B1PAD + n];
                b.y = wb[(k0 + tig + 4) * B1PAD + n];
                mma_tf32(acc[j], af, b);
            }
        }
    }

    const int r0g = m0g + wm * 16 + gq;
#pragma unroll
    for (int j = 0; j < 5; j++) {
        const int n = wn * 40 + j * 8 + tig * 2;
        *(float2*)&g_h[(size_t)r0g * NMIX + n] =
            make_float2(tanhf(acc[j][0]), tanhf(acc[j][1]));
        *(float2*)&g_h[(size_t)(r0g + 8) * NMIX + n] =
            make_float2(tanhf(acc[j][2]), tanhf(acc[j][3]));
    }
#undef LDG1
#undef STS1
}

// ---------------------------------------------------------------------------
// GEMM2 fused: out[m,f,d] = x + sx*(maa_f + h_f @ W2_f)
// 64m x 256d block; h staged once; W2 in 32-wide double-buffered chunks;
// one barrier per chunk; state copy folded in.
// ---------------------------------------------------------------------------
__global__ void __launch_bounds__(T2, 2) k_gemm2(
    const float* __restrict__ x, const float* __restrict__ state,
    const float* __restrict__ W2,
    const float* __restrict__ mk, const float* __restrict__ mw,
    const float* __restrict__ mv, const float* __restrict__ mr,
    const float* __restrict__ mg,
    const int* __restrict__ i_ptr, float* __restrict__ out,
    float* __restrict__ out_state,
    int S, int D, int rows, int has_state, int total4)
{
    extern __shared__ float sm[];
    float* h_s = sm;                 // [64][HPAD]
    float* wb0 = sm + HS_SZ;         // [2][160][WPAD2]

    const int m0   = blockIdx.x * BM2;
    const int d0   = blockIdx.y * BN2;
    const int tid  = threadIdx.x;
    const int w    = tid >> 5;
    const int lane = tid & 31;
    const int wm   = w & 3;          // 4 m-groups of 16
    const int wn   = w >> 2;         // 2 n-groups of 16 (within 32-chunk)
    const int gq   = lane >> 2;
    const int tig  = lane & 3;
    const int i1   = rows * i_ptr[0] + 1;

    // ---- state copy (distributed over all blocks) ----
    if (has_state) {
        const int nb = gridDim.x * gridDim.y;
        for (int idx = (blockIdx.y * gridDim.x + blockIdx.x) * T2 + tid;
             idx < total4; idx += nb * T2) {
            int e  = idx * 4;
            int dd = e % D;
            int r  = (e / D) % rows;
            int b  = e / (D * rows);
            float4 v;
            if (r == i1)
                v = *(const float4*)&x[((size_t)b * S + (S - 1)) * D + dd];
            else
                v = *(const float4*)&state[e];
            *(float4*)&out_state[e] = v;
        }
    }

    // ---- stage h (64x160), once per block ----
#pragma unroll
    for (int it = 0; it < 10; it++) {
        int idx = tid + it * T2;
        int r   = idx / 40;
        int c4  = (idx - r * 40) * 4;
        *(float4*)&h_s[r * HPAD + c4] = *(const float4*)&g_h[(size_t)(m0 + r) * NMIX + c4];
    }

    const float* maa[5] = { mk, mw, mv, mr, mg };

    // W2 chunk staging: 160 x 32 floats = 1280 float4, 5 per thread
    float4 w2v[5];

#define LDGW(C)                                                               \
    {                                                                         \
        _Pragma("unroll")                                                     \
        for (int it = 0; it < 5; it++) {                                      \
            int idx = tid + it * T2;                                          \
            int k   = idx >> 3;                                               \
            int n4  = (idx & 7) * 4;                                          \
            w2v[it] = *(const float4*)&W2[(size_t)k * D + d0 + (C) * CW + n4]; \
        }                                                                     \
    }

#define STSW(BUF)                                                             \
    {                                                                         \
        float* wb = wb0 + (BUF) * WB_SZ;                                      \
        _Pragma("unroll")                                                     \
        for (int it = 0; it < 5; it++) {                                      \
            int idx = tid + it * T2;                                          \
            int k   = idx >> 3;                                               \
            int n4  = (idx & 7) * 4;                                          \
            *(float4*)&wb[k * WPAD2 + n4] = w2v[it];                          \
        }                                                                     \
    }

    LDGW(0);

    for (int c = 0; c < NCH; c++) {
        STSW(c & 1);
        __syncthreads();                 // also covers h_s staging (c==0)
        if (c + 1 < NCH) LDGW(c + 1);

        const float* wb = wb0 + (c & 1) * WB_SZ;
        const int d0c = d0 + c * CW;
        const int r0  = wm * 16 + gq;

        float acc[5][2][4];
#pragma unroll
        for (int f = 0; f < 5; f++)
#pragma unroll
            for (int j = 0; j < 2; j++)
#pragma unroll
                for (int q = 0; q < 4; q++) acc[f][j][q] = 0.f;

#pragma unroll
        for (int f = 0; f < 5; f++) {
#pragma unroll
            for (int ks = 0; ks < 4; ks++) {
                const int kc = f * 32 + ks * 8;
                float4 af;
                af.x = h_s[r0 * HPAD + kc + tig];
                af.y = h_s[(r0 + 8) * HPAD + kc + tig];
                af.z = h_s[r0 * HPAD + kc + tig + 4];
                af.w = h_s[(r0 + 8) * HPAD + kc + tig + 4];
#pragma unroll
                for (int j = 0; j < 2; j++) {
                    const int n = wn * 16 + j * 8 + gq;
                    float2 b;
                    b.x = wb[(kc + tig) * WPAD2 + n];
                    b.y = wb[(kc + tig + 4) * WPAD2 + n];
                    mma_tf32(acc[f][j], af, b);
                }
            }
        }

        // epilogue for this 32-wide chunk; f innermost
#pragma unroll
        for (int j = 0; j < 2; j++) {
            const int d = d0c + wn * 16 + j * 8 + tig * 2;
            float2 m2[5];
#pragma unroll
            for (int f = 0; f < 5; f++) m2[f] = *(const float2*)&maa[f][d];
#pragma unroll
            for (int half = 0; half < 2; half++) {
                const int mr_ = m0 + wm * 16 + gq + half * 8;
                const float2 xvv = *(const float2*)&x[(size_t)mr_ * D + d];
                float2 pvv;
                if ((mr_ % S) == 0) {
                    int b = mr_ / S;
                    pvv = *(const float2*)&state[((size_t)b * rows + i1) * D + d];
                } else {
                    pvv = *(const float2*)&x[(size_t)(mr_ - 1) * D + d];
                }
                const float sx0 = pvv.x - xvv.x;
                const float sx1 = pvv.y - xvv.y;
#pragma unroll
                for (int f = 0; f < 5; f++) {
                    float2 o;
                    o.x = xvv.x + sx0 * (m2[f].x + acc[f][j][half * 2]);
                    o.y = xvv.y + sx1 * (m2[f].y + acc[f][j][half * 2 + 1]);
                    *(float2*)&out[((size_t)mr_ * 5 + f) * D + d] = o;
                }
            }
        }
    }
#undef LDGW
#undef STSW
}

// ---------------------------------------------------------------------------
extern "C" void kernel_launch(void* const* d_in, const int* in_sizes, int n_in,
                              void* d_out, int out_size)
{
    const float* x     = (const float*)d_in[0];
    const float* state = (const float*)d_in[1];
    const float* tmx   = (const float*)d_in[2];
    const float* W1    = (const float*)d_in[3];
    const float* W2    = (const float*)d_in[4];
    const float* mk    = (const float*)d_in[5];
    const float* mw    = (const float*)d_in[6];
    const float* mv    = (const float*)d_in[7];
    const float* mr    = (const float*)d_in[8];
    const float* mg    = (const float*)d_in[9];
    const int*   ip    = (const int*)d_in[10];

    const int D    = in_sizes[2];          // 2048
    const int M    = in_sizes[0] / D;      // 8192
    const int rows = 2 + D / 32;           // 66
    const int B    = in_sizes[1] / (rows * D);
    const int S    = M / B;

    float* out_x = (float*)d_out;
    const long long xsz = (long long)M * 5 * D;
    const int has_state = ((long long)out_size > xsz) ? 1 : 0;
    float* out_state = out_x + xsz;
    const int total4 = (B * rows * D) / 4;

    const int smem1 = SM1_FLOATS * 4;      // 120832 B
    const int smem2 = SM2_FLOATS * 4;      // 93184 B
    static int inited = 0;
    if (!inited) {
        cudaFuncSetAttribute(k_gemm1, cudaFuncAttributeMaxDynamicSharedMemorySize, smem1);
        cudaFuncSetAttribute(k_gemm2, cudaFuncAttributeMaxDynamicSharedMemorySize, smem2);
        inited = 1;
    }

    k_gemm1<<<M / BM1, T1, smem1>>>(x, state, tmx, W1, ip, S, D, rows);

    dim3 g2(M / BM2, D / BN2);
    k_gemm2<<<g2, T2, smem2>>>(x, state, W2, mk, mw, mv, mr, mg, ip,
                               out_x, out_state, S, D, rows,
                               has_state, total4);
}

// round 11
// speedup vs baseline: 1.3833x; 1.0609x over previous
#include <cuda_runtime.h>

#define NMIX 160
// gemm1: 64m x 160n, KC=64, 512 threads = 4m x 4n warps, j=5
#define T1    512
#define BM1   64
#define KC1   64
#define A1PAD 68     // mod 32 = 4  (A-frag conflict-free)
#define B1PAD 168    // mod 32 = 8  (B-frag conflict-free)
#define XK_SZ (BM1 * A1PAD)
#define W1_SZ (KC1 * B1PAD)
#define SM1_FLOATS (2 * XK_SZ + 2 * W1_SZ)       // 30208 -> 120832 B
// gemm2: 64m x 256d blocks; W2 in 32-wide chunks; y restaged per chunk
#define T2    256
#define BM2   64
#define BN2   256
#define CW    32
#define NCH   (BN2 / CW)             // 8
#define HPADP 168                    // paired-h row len (mod 32 = 8)
#define WPAD2 40                     // mod 32 = 8
#define YP    36                     // y row len (mod 32 = 4)
#define HS_SZ  (BM2 * HPADP)                     // 10752
#define WB_SZ  (NMIX * WPAD2)                    // 6400
#define YS_SZ  (5 * BM2 * YP)                    // 11520
#define OFF_W2 HS_SZ
#define OFF_Y  (HS_SZ + WB_SZ)
#define SM2_FLOATS (HS_SZ + WB_SZ + YS_SZ)       // 28672 -> 114688 B

// h = tanh(xk @ W1): [M][NMIX], M = 8192
__device__ float g_h[8192 * NMIX];

__device__ __forceinline__ void mma_tf32(float* c, const float4& a, const float2& b) {
    const unsigned* A = reinterpret_cast<const unsigned*>(&a);
    const unsigned* B = reinterpret_cast<const unsigned*>(&b);
    asm volatile(
        "mma.sync.aligned.m16n8k8.row.col.f32.tf32.tf32.f32 "
        "{%0,%1,%2,%3},{%4,%5,%6,%7},{%8,%9},{%0,%1,%2,%3};"
        : "+f"(c[0]), "+f"(c[1]), "+f"(c[2]), "+f"(c[3])
        : "r"(A[0]), "r"(A[1]), "r"(A[2]), "r"(A[3]), "r"(B[0]), "r"(B[1]));
}

__device__ __forceinline__ void mma_tf32_p(float* c, const float2& alo,
                                           const float2& ahi, const float2& b) {
    // A fragment order: {A[gq][t], A[gq+8][t], A[gq][t+4], A[gq+8][t+4]}
    const unsigned* L = reinterpret_cast<const unsigned*>(&alo);
    const unsigned* H = reinterpret_cast<const unsigned*>(&ahi);
    const unsigned* B = reinterpret_cast<const unsigned*>(&b);
    asm volatile(
        "mma.sync.aligned.m16n8k8.row.col.f32.tf32.tf32.f32 "
        "{%0,%1,%2,%3},{%4,%5,%6,%7},{%8,%9},{%0,%1,%2,%3};"
        : "+f"(c[0]), "+f"(c[1]), "+f"(c[2]), "+f"(c[3])
        : "r"(L[0]), "r"(H[0]), "r"(L[1]), "r"(H[1]), "r"(B[0]), "r"(B[1]));
}

// ---------------------------------------------------------------------------
// GEMM1: g_h[m,n] = tanh( sum_k xk[m,k] * W1[k,n] )   (unchanged from R10)
// ---------------------------------------------------------------------------
__global__ void __launch_bounds__(T1, 1) k_gemm1(
    const float* __restrict__ x, const float* __restrict__ state,
    const float* __restrict__ tmx, const float* __restrict__ W1,
    const int* __restrict__ i_ptr, int S, int D, int rows)
{
    extern __shared__ float sm[];

    const int m0g  = blockIdx.x * BM1;
    const int tid  = threadIdx.x;
    const int w    = tid >> 5;
    const int lane = tid & 31;
    const int wm   = w & 3;
    const int wn   = w >> 2;
    const int gq   = lane >> 2;
    const int tig  = lane & 3;
    const int i1   = rows * i_ptr[0] + 1;

    const int sa_m  = tid >> 4;
    const int sa_kq = (tid & 15) * 4;

    float acc[5][4];
#pragma unroll
    for (int j = 0; j < 5; j++)
#pragma unroll
        for (int q = 0; q < 4; q++) acc[j][q] = 0.f;

    float4 xv[2], pv[2], tv[2];
    float4 wv[5];
    int    wk[5], wn4[5];

    const int nc = D / KC1;

#define LDG1(KB)                                                              \
    {                                                                         \
        _Pragma("unroll")                                                     \
        for (int it = 0; it < 2; it++) {                                      \
            int m  = sa_m + it * 32;                                          \
            int mg = m0g + m;                                                 \
            int g  = (KB) + sa_kq;                                            \
            xv[it] = *(const float4*)&x[(size_t)mg * D + g];                  \
            if ((mg % S) == 0) {                                              \
                int b = mg / S;                                               \
                pv[it] = *(const float4*)&state[((size_t)b * rows + i1) * D + g]; \
            } else {                                                          \
                pv[it] = *(const float4*)&x[(size_t)(mg - 1) * D + g];        \
            }                                                                 \
            tv[it] = *(const float4*)&tmx[g];                                 \
        }                                                                     \
        _Pragma("unroll")                                                     \
        for (int it = 0; it < 5; it++) {                                      \
            int idx = tid + it * T1;                                          \
            int k   = idx / 40;                                               \
            int n4  = (idx - k * 40) * 4;                                     \
            wk[it] = k; wn4[it] = n4;                                         \
            wv[it] = *(const float4*)&W1[(size_t)((KB) + k) * NMIX + n4];     \
        }                                                                     \
    }

#define STS1(BUF)                                                             \
    {                                                                         \
        float* xb = sm + (BUF) * XK_SZ;                                       \
        float* wb = sm + 2 * XK_SZ + (BUF) * W1_SZ;                           \
        _Pragma("unroll")                                                     \
        for (int it = 0; it < 2; it++) {                                      \
            int m = sa_m + it * 32;                                           \
            float4 v;                                                         \
            v.x = xv[it].x + (pv[it].x - xv[it].x) * tv[it].x;                \
            v.y = xv[it].y + (pv[it].y - xv[it].y) * tv[it].y;                \
            v.z = xv[it].z + (pv[it].z - xv[it].z) * tv[it].z;                \
            v.w = xv[it].w + (pv[it].w - xv[it].w) * tv[it].w;                \
            *(float4*)&xb[m * A1PAD + sa_kq] = v;                             \
        }                                                                     \
        _Pragma("unroll")                                                     \
        for (int it = 0; it < 5; it++)                                        \
            *(float4*)&wb[wk[it] * B1PAD + wn4[it]] = wv[it];                 \
    }

    LDG1(0);

    for (int c = 0; c < nc; c++) {
        STS1(c & 1);
        __syncthreads();
        if (c + 1 < nc) LDG1((c + 1) * KC1);

        const float* xb = sm + (c & 1) * XK_SZ;
        const float* wb = sm + 2 * XK_SZ + (c & 1) * W1_SZ;
        const int r0 = wm * 16 + gq;
#pragma unroll
        for (int ks = 0; ks < 8; ks++) {
            const int k0 = ks * 8;
            float4 af;
            af.x = xb[r0 * A1PAD + k0 + tig];
            af.y = xb[(r0 + 8) * A1PAD + k0 + tig];
            af.z = xb[r0 * A1PAD + k0 + tig + 4];
            af.w = xb[(r0 + 8) * A1PAD + k0 + tig + 4];
#pragma unroll
            for (int j = 0; j < 5; j++) {
                const int n = wn * 40 + j * 8 + gq;
                float2 b;
                b.x = wb[(k0 + tig) * B1PAD + n];
                b.y = wb[(k0 + tig + 4) * B1PAD + n];
                mma_tf32(acc[j], af, b);
            }
        }
    }

    const int r0g = m0g + wm * 16 + gq;
#pragma unroll
    for (int j = 0; j < 5; j++) {
        const int n = wn * 40 + j * 8 + tig * 2;
        *(float2*)&g_h[(size_t)r0g * NMIX + n] =
            make_float2(tanhf(acc[j][0]), tanhf(acc[j][1]));
        *(float2*)&g_h[(size_t)(r0g + 8) * NMIX + n] =
            make_float2(tanhf(acc[j][2]), tanhf(acc[j][3]));
    }
#undef LDG1
#undef STS1
}

// ---------------------------------------------------------------------------
// GEMM2 fused: out[m,f,d] = x + sx*(maa_f + h_f @ W2_f)
// 64m x 256d block; paired-h; y restage -> coalesced epilogue; 2 bars/chunk.
// ---------------------------------------------------------------------------
__global__ void __launch_bounds__(T2, 2) k_gemm2(
    const float* __restrict__ x, const float* __restrict__ state,
    const float* __restrict__ W2,
    const float* __restrict__ mk, const float* __restrict__ mw,
    const float* __restrict__ mv, const float* __restrict__ mr,
    const float* __restrict__ mg,
    const int* __restrict__ i_ptr, float* __restrict__ out,
    float* __restrict__ out_state,
    int S, int D, int rows, int has_state, int total4)
{
    extern __shared__ float sm[];
    float* hp  = sm;                 // paired h: [64][HPADP]
    float* w2s = sm + OFF_W2;        // [160][WPAD2], k-major
    float* ys  = sm + OFF_Y;         // [5][64][YP]

    const int m0   = blockIdx.x * BM2;
    const int d0   = blockIdx.y * BN2;
    const int tid  = threadIdx.x;
    const int w    = tid >> 5;
    const int lane = tid & 31;
    const int wm   = w & 3;          // 4 m-groups of 16
    const int wn   = w >> 2;         // 2 n-groups of 16 (within 32-chunk)
    const int gq   = lane >> 2;
    const int tig  = lane & 3;
    const int i1   = rows * i_ptr[0] + 1;

    // ---- state copy (distributed over all blocks) ----
    if (has_state) {
        const int nb = gridDim.x * gridDim.y;
        for (int idx = (blockIdx.y * gridDim.x + blockIdx.x) * T2 + tid;
             idx < total4; idx += nb * T2) {
            int e  = idx * 4;
            int dd = e % D;
            int r  = (e / D) % rows;
            int b  = e / (D * rows);
            float4 v;
            if (r == i1)
                v = *(const float4*)&x[((size_t)b * S + (S - 1)) * D + dd];
            else
                v = *(const float4*)&state[e];
            *(float4*)&out_state[e] = v;
        }
    }

    // ---- stage h (64x160) once, in PAIRED layout:
    //      hp[r][ks*8 + tig*2 + half] = h[r][ks*8 + half*4 + tig] ----
#pragma unroll
    for (int it = 0; it < 10; it++) {
        int idx = tid + it * T2;
        int r   = idx / 40;
        int c4  = (idx - r * 40) * 4;
        const float4 hv = *(const float4*)&g_h[(size_t)(m0 + r) * NMIX + c4];
        int ks   = c4 >> 3;
        int half = (c4 >> 2) & 1;
        float* dst = &hp[r * HPADP + ks * 8 + half];
        dst[0] = hv.x; dst[2] = hv.y; dst[4] = hv.z; dst[6] = hv.w;
    }

    const float* maa[5] = { mk, mw, mv, mr, mg };

    // epilogue thread mapping: 4-line coalesced
    const int er  = tid >> 3;            // row 0..31 (+32 second pass)
    const int ec4 = (tid & 7) * 4;       // col 0..28

    float4 w2v[5];

#define LDGW(C)                                                               \
    {                                                                         \
        _Pragma("unroll")                                                     \
        for (int it = 0; it < 5; it++) {                                      \
            int idx = tid + it * T2;                                          \
            int k   = idx >> 3;                                               \
            int n4  = (idx & 7) * 4;                                          \
            w2v[it] = *(const float4*)&W2[(size_t)k * D + d0 + (C) * CW + n4]; \
        }                                                                     \
    }

#define STSW()                                                                \
    {                                                                         \
        _Pragma("unroll")                                                     \
        for (int it = 0; it < 5; it++) {                                      \
            int idx = tid + it * T2;                                          \
            int k   = idx >> 3;                                               \
            int n4  = (idx & 7) * 4;                                          \
            *(float4*)&w2s[k * WPAD2 + n4] = w2v[it];                         \
        }                                                                     \
    }

    LDGW(0);

    for (int c = 0; c < NCH; c++) {
        STSW();
        __syncthreads();                 // (A) w2s ready; also h staging (c==0)
        if (c + 1 < NCH) LDGW(c + 1);

        const int d0c = d0 + c * CW;
        const int r0  = wm * 16 + gq;

        float acc[5][2][4];
#pragma unroll
        for (int f = 0; f < 5; f++)
#pragma unroll
            for (int j = 0; j < 2; j++)
#pragma unroll
                for (int q = 0; q < 4; q++) acc[f][j][q] = 0.f;

#pragma unroll
        for (int f = 0; f < 5; f++) {
#pragma unroll
            for (int ks = 0; ks < 4; ks++) {
                const int kf = (f * 4 + ks) * 8;   // paired pos base
                const float2 alo = *(const float2*)&hp[r0 * HPADP + kf + tig * 2];
                const float2 ahi = *(const float2*)&hp[(r0 + 8) * HPADP + kf + tig * 2];
                const int kc = f * 32 + ks * 8;
#pragma unroll
                for (int j = 0; j < 2; j++) {
                    const int n = wn * 16 + j * 8 + gq;
                    float2 b;
                    b.x = w2s[(kc + tig) * WPAD2 + n];
                    b.y = w2s[(kc + tig + 4) * WPAD2 + n];
                    mma_tf32_p(acc[f][j], alo, ahi, b);
                }
            }
        }

        // ---- restage y fragments to smem ----
#pragma unroll
        for (int f = 0; f < 5; f++)
#pragma unroll
            for (int j = 0; j < 2; j++) {
                const int col = wn * 16 + j * 8 + tig * 2;
#pragma unroll
                for (int half = 0; half < 2; half++) {
                    const int row = wm * 16 + gq + half * 8;
                    *(float2*)&ys[(f * BM2 + row) * YP + col] =
                        make_float2(acc[f][j][half * 2], acc[f][j][half * 2 + 1]);
                }
            }
        __syncthreads();                 // (B) y ready

        // ---- coalesced epilogue: thread -> (row, 4 consecutive d) ----
#pragma unroll
        for (int it = 0; it < 2; it++) {
            const int row = er + it * 32;
            const int mr_ = m0 + row;
            const float4 xvv = *(const float4*)&x[(size_t)mr_ * D + d0c + ec4];
            float4 pvv;
            if ((mr_ % S) == 0) {
                int b = mr_ / S;
                pvv = *(const float4*)&state[((size_t)b * rows + i1) * D + d0c + ec4];
            } else {
                pvv = *(const float4*)&x[(size_t)(mr_ - 1) * D + d0c + ec4];
            }
            float4 sxv;
            sxv.x = pvv.x - xvv.x; sxv.y = pvv.y - xvv.y;
            sxv.z = pvv.z - xvv.z; sxv.w = pvv.w - xvv.w;
#pragma unroll
            for (int f = 0; f < 5; f++) {
                const float4 mfv = *(const float4*)&maa[f][d0c + ec4];
                const float4 yv  = *(const float4*)&ys[(f * BM2 + row) * YP + ec4];
                float4 o;
                o.x = xvv.x + sxv.x * (mfv.x + yv.x);
                o.y = xvv.y + sxv.y * (mfv.y + yv.y);
                o.z = xvv.z + sxv.z * (mfv.z + yv.z);
                o.w = xvv.w + sxv.w * (mfv.w + yv.w);
                *(float4*)&out[((size_t)mr_ * 5 + f) * D + d0c + ec4] = o;
            }
        }
    }
#undef LDGW
#undef STSW
}

// ---------------------------------------------------------------------------
extern "C" void kernel_launch(void* const* d_in, const int* in_sizes, int n_in,
                              void* d_out, int out_size)
{
    const float* x     = (const float*)d_in[0];
    const float* state = (const float*)d_in[1];
    const float* tmx   = (const float*)d_in[2];
    const float* W1    = (const float*)d_in[3];
    const float* W2    = (const float*)d_in[4];
    const float* mk    = (const float*)d_in[5];
    const float* mw    = (const float*)d_in[6];
    const float* mv    = (const float*)d_in[7];
    const float* mr    = (const float*)d_in[8];
    const float* mg    = (const float*)d_in[9];
    const int*   ip    = (const int*)d_in[10];

    const int D    = in_sizes[2];          // 2048
    const int M    = in_sizes[0] / D;      // 8192
    const int rows = 2 + D / 32;           // 66
    const int B    = in_sizes[1] / (rows * D);
    const int S    = M / B;

    float* out_x = (float*)d_out;
    const long long xsz = (long long)M * 5 * D;
    const int has_state = ((long long)out_size > xsz) ? 1 : 0;
    float* out_state = out_x + xsz;
    const int total4 = (B * rows * D) / 4;

    const int smem1 = SM1_FLOATS * 4;      // 120832 B
    const int smem2 = SM2_FLOATS * 4;      // 114688 B
    static int inited = 0;
    if (!inited) {
        cudaFuncSetAttribute(k_gemm1, cudaFuncAttributeMaxDynamicSharedMemorySize, smem1);
        cudaFuncSetAttribute(k_gemm2, cudaFuncAttributeMaxDynamicSharedMemorySize, smem2);
        inited = 1;
    }

    k_gemm1<<<M / BM1, T1, smem1>>>(x, state, tmx, W1, ip, S, D, rows);

    dim3 g2(M / BM2, D / BN2);
    k_gemm2<<<g2, T2, smem2>>>(x, state, W2, mk, mw, mv, mr, mg, ip,
                               out_x, out_state, S, D, rows,
                               has_state, total4);
}